// round 1
// baseline (speedup 1.0000x reference)
#include <cuda_runtime.h>

#define BB 4
#define CC 256
#define HH 64
#define WW 64
#define H2 128
#define W2 128
#define HW   (HH*WW)    // 4096
#define HW2  (H2*W2)    // 16384

// Scratch (no allocation allowed)
__device__ float g_dec[BB*25*HW];     // conv1x1(de, W_cd)             [b][k][h][w]
__device__ float g_gate[BB*HW];       // conv1x1(de, W_gate)+b (pre-sigmoid, lowres)
__device__ float g_enc[BB*25*HW2];    // conv1x1(en, W_ce)+b_ce        [b][k][i][j]
__device__ float g_raw[BB*25*HW2];    // pre-softmax kernel logits

typedef unsigned long long u64;

__device__ __forceinline__ u64 pack2(float x, float y){
    u64 r; asm("mov.b64 %0, {%1, %2};" : "=l"(r) : "f"(x), "f"(y)); return r;
}
__device__ __forceinline__ void unpack2(u64 v, float &x, float &y){
    asm("mov.b64 {%0, %1}, %2;" : "=f"(x), "=f"(y) : "l"(v));
}
__device__ __forceinline__ void ffma2(u64 &d, u64 a, u64 b){
    asm("fma.rn.f32x2 %0, %1, %2, %0;" : "+l"(d) : "l"(a), "l"(b));
}

// ---------------------------------------------------------------------------
// K1: dec[b,k,h,w] = sum_c de[b,c,h,w]*W_cd[k,c]   (25 outputs, no bias)
//     gatepre[b,h,w] = sum_c de*W_gate[c] + b_gate (output #25)
// 26 outputs -> 13 packed f32x2 accumulators. 1 lowres pixel / thread.
// ---------------------------------------------------------------------------
__global__ __launch_bounds__(128) void k1_dec_gate(
        const float* __restrict__ de, const float* __restrict__ W_cd,
        const float* __restrict__ W_gate, const float* __restrict__ b_gate)
{
    __shared__ u64 pw[13*256];   // pw[p][c] = (out(2p,c), out(2p+1,c))
    int tid = threadIdx.x;
    for (int idx = tid; idx < 13*256; idx += 128){
        int p = idx >> 8, c = idx & 255;
        int o0 = 2*p, o1 = 2*p+1;
        float w0 = (o0 < 25) ? W_cd[o0*256 + c] : W_gate[c];
        float w1 = (o1 < 25) ? W_cd[o1*256 + c] : W_gate[c];
        pw[idx] = pack2(w0, w1);
    }
    __syncthreads();

    int t = blockIdx.x*128 + tid;         // 16384 threads total
    int b = t >> 12, pix = t & 4095;
    const float* dp = de + (b<<8)*HW + pix;

    u64 acc[13];
    #pragma unroll
    for (int p=0;p<13;p++) acc[p] = 0ULL;

    #pragma unroll 4
    for (int c=0;c<256;c++){
        float v = dp[c*HW];
        u64 vd = pack2(v, v);
        #pragma unroll
        for (int p=0;p<13;p++) ffma2(acc[p], vd, pw[(p<<8)+c]);
    }

    float o[26];
    #pragma unroll
    for (int p=0;p<13;p++) unpack2(acc[p], o[2*p], o[2*p+1]);
    #pragma unroll
    for (int k=0;k<25;k++) g_dec[(b*25+k)*HW + pix] = o[k];
    g_gate[b*HW + pix] = o[25] + b_gate[0];
}

// ---------------------------------------------------------------------------
// K2: enc[b,k,i,j] = sum_c en[b,c,i,j]*W_ce[k,c] + b_ce[k]
// 4 hires pixels / thread (float4). Outputs packed pairwise over k:
// acc[p][x] = (enc_{2p}, enc_{2p+1}) for pixel x.
// ---------------------------------------------------------------------------
__global__ __launch_bounds__(128) void k2_enc(
        const float* __restrict__ en, const float* __restrict__ W_ce,
        const float* __restrict__ b_ce)
{
    __shared__ __align__(8) float sw[256*26];    // sw[c*26 + r] = W_ce[r][c], r=25 pad 0
    int tid = threadIdx.x;
    for (int idx = tid; idx < 256*26; idx += 128){
        int c = idx / 26, r = idx - c*26;
        sw[idx] = (r < 25) ? W_ce[r*256 + c] : 0.f;
    }
    __syncthreads();

    int q = blockIdx.x*128 + tid;        // quad index, 16384 total
    int b = q >> 12;
    int pix = (q & 4095) << 2;
    const float4* ep = (const float4*)(en + (b<<8)*HW2 + pix);

    u64 acc[13][4];
    #pragma unroll
    for (int p=0;p<13;p++){
        #pragma unroll
        for (int x=0;x<4;x++) acc[p][x] = 0ULL;
    }

    #pragma unroll 2
    for (int c=0;c<256;c++){
        float4 e = ep[c*4096];
        u64 v0 = pack2(e.x,e.x), v1 = pack2(e.y,e.y);
        u64 v2 = pack2(e.z,e.z), v3 = pack2(e.w,e.w);
        const u64* wc = (const u64*)(sw + c*26);
        #pragma unroll
        for (int p=0;p<13;p++){
            u64 wpk = wc[p];
            ffma2(acc[p][0], v0, wpk);
            ffma2(acc[p][1], v1, wpk);
            ffma2(acc[p][2], v2, wpk);
            ffma2(acc[p][3], v3, wpk);
        }
    }

    #pragma unroll
    for (int p=0;p<13;p++){
        float a0x,a0y,a1x,a1y,a2x,a2y,a3x,a3y;
        unpack2(acc[p][0],a0x,a0y); unpack2(acc[p][1],a1x,a1y);
        unpack2(acc[p][2],a2x,a2y); unpack2(acc[p][3],a3x,a3y);
        int k0 = 2*p;
        float bb0 = b_ce[k0];
        float4 v; v.x=a0x+bb0; v.y=a1x+bb0; v.z=a2x+bb0; v.w=a3x+bb0;
        *(float4*)(g_enc + (b*25+k0)*HW2 + pix) = v;
        if (k0+1 < 25){
            float bb1 = b_ce[k0+1];
            float4 u; u.x=a0y+bb1; u.y=a1y+bb1; u.z=a2y+bb1; u.w=a3y+bb1;
            *(float4*)(g_enc + (b*25+k0+1)*HW2 + pix) = u;
        }
    }
}

// ---------------------------------------------------------------------------
// K3: raw[b,k,i,j] = dw3x3(enc)[i,j] + dw3x3(dec)[i/2,j/2] + 2*b_dw[k]
// (reference adds b_dw in both depthwise convs)
// ---------------------------------------------------------------------------
__global__ __launch_bounds__(256) void k3_raw(
        const float* __restrict__ W_dw, const float* __restrict__ b_dw)
{
    int bk = blockIdx.y;                 // b*25 + k
    int k = bk % 25;
    __shared__ float sw[9];
    __shared__ float sbias;
    if (threadIdx.x < 9)  sw[threadIdx.x] = W_dw[k*9 + threadIdx.x];
    if (threadIdx.x == 9) sbias = b_dw[k];
    __syncthreads();

    int p = blockIdx.x*256 + threadIdx.x;
    int i = p >> 7, j = p & 127;
    const float* e = g_enc + bk*HW2;
    const float* d = g_dec + bk*HW;

    float acc = 2.f * sbias;
    #pragma unroll
    for (int u=0;u<3;u++){
        int ii = i + u - 1;
        if ((unsigned)ii < 128u){
            #pragma unroll
            for (int v=0;v<3;v++){
                int jj = j + v - 1;
                if ((unsigned)jj < 128u) acc += e[ii*128 + jj] * sw[u*3+v];
            }
        }
    }
    int h = i >> 1, w = j >> 1;
    #pragma unroll
    for (int u=0;u<3;u++){
        int hh = h + u - 1;
        if ((unsigned)hh < 64u){
            #pragma unroll
            for (int v=0;v<3;v++){
                int ww = w + v - 1;
                if ((unsigned)ww < 64u) acc += d[hh*64 + ww] * sw[u*3+v];
            }
        }
    }
    g_raw[bk*HW2 + p] = acc;
}

// ---------------------------------------------------------------------------
// K4: softmax(raw) -> 25 weights per hires pixel (packed (w,w) in regs),
// then carafe over 256 channels (2 channels per f32x2 FMA, de staged in smem
// with channel-pair interleaving), fused with gate blend of en.
// Block: 16x4 lowres tile (32x8 hires). tid = lowres_pixel*4 + subpixel so a
// warp covers 8 consecutive lowres pixels -> conflict-free broadcast LDS.
// ---------------------------------------------------------------------------
__global__ __launch_bounds__(256) void k4_out(
        const float* __restrict__ en, const float* __restrict__ de,
        float* __restrict__ out)
{
    int tid = threadIdx.x;
    int sub = tid & 3, lp = tid >> 2;      // lp: 0..63
    int lw = lp & 15,  lh = lp >> 4;       // 16 x 4 lowres tile
    int b  = blockIdx.z;
    int w0 = blockIdx.x * 16, h0 = blockIdx.y * 4;
    int hcur = h0 + lh, wcur = w0 + lw;
    int i = 2*hcur + (sub >> 1), j = 2*wcur + (sub & 1);

    // softmax weights
    float r[25];
    const float* rp = g_raw + (b*25)*HW2 + i*128 + j;
    #pragma unroll
    for (int k=0;k<25;k++) r[k] = rp[k*HW2];
    float m = r[0];
    #pragma unroll
    for (int k=1;k<25;k++) m = fmaxf(m, r[k]);
    float s = 0.f;
    #pragma unroll
    for (int k=0;k<25;k++){ r[k] = __expf(r[k]-m); s += r[k]; }
    float inv = 1.f / s;
    u64 wp[25];
    #pragma unroll
    for (int k=0;k<25;k++){ float wv = r[k]*inv; wp[k] = pack2(wv, wv); }

    // gate
    float gpre = g_gate[b*HW + hcur*64 + wcur];
    float g  = 1.f / (1.f + __expf(-gpre));
    float ga = 1.f - g;

    __shared__ __align__(16) float sde[4*160*2];  // [pair][pix 8x20][2 channels]
    int outbase = (b<<8)*HW2 + i*128 + j;
    int sbase = (lh*20 + lw) << 1;                // float offset within a pair block

    for (int chunk = 0; chunk < 32; chunk++){
        int cbase = chunk << 3;
        // stage 8 channels of the (8 x 20) lowres tile (halo r=2, zero pad)
        #pragma unroll 5
        for (int idx = tid; idx < 1280; idx += 256){
            int ch  = idx / 160;
            int pix = idx - ch*160;
            int py = pix / 20, px = pix - py*20;
            int hh = h0 - 2 + py, ww = w0 - 2 + px;
            float v = 0.f;
            if ((unsigned)hh < 64u && (unsigned)ww < 64u)
                v = de[((b<<8) + cbase + ch)*HW + hh*64 + ww];
            int pr = ch >> 1, half = ch & 1;
            sde[((pr*160 + pix) << 1) + half] = v;
        }
        __syncthreads();

        #pragma unroll
        for (int pr=0; pr<4; pr++){
            u64 acc = 0ULL;
            const u64* sp = (const u64*)(sde + pr*320 + sbase);
            #pragma unroll
            for (int dy=0; dy<5; dy++){
                #pragma unroll
                for (int dx=0; dx<5; dx++){
                    ffma2(acc, sp[dy*20 + dx], wp[dy*5 + dx]);
                }
            }
            float a0, a1; unpack2(acc, a0, a1);
            int o0 = outbase + (cbase + pr*2)*HW2;
            out[o0]       = fmaf(g, en[o0],       ga*a0);
            out[o0 + HW2] = fmaf(g, en[o0 + HW2], ga*a1);
        }
        __syncthreads();
    }
}

// ---------------------------------------------------------------------------
extern "C" void kernel_launch(void* const* d_in, const int* in_sizes, int n_in,
                              void* d_out, int out_size)
{
    const float* en     = (const float*)d_in[0];
    const float* de     = (const float*)d_in[1];
    const float* W_gate = (const float*)d_in[2];
    const float* b_gate = (const float*)d_in[3];
    const float* W_ce   = (const float*)d_in[4];
    const float* b_ce   = (const float*)d_in[5];
    const float* W_cd   = (const float*)d_in[6];
    const float* W_dw   = (const float*)d_in[7];
    const float* b_dw   = (const float*)d_in[8];
    float* out = (float*)d_out;

    k1_dec_gate<<<128, 128>>>(de, W_cd, W_gate, b_gate);
    k2_enc<<<128, 128>>>(en, W_ce, b_ce);
    k3_raw<<<dim3(64, BB*25), 256>>>(W_dw, b_dw);
    k4_out<<<dim3(4, 16, BB), 256>>>(en, de, out);
}

// round 2
// speedup vs baseline: 1.4270x; 1.4270x over previous
#include <cuda_runtime.h>

#define HW   4096     // 64*64
#define HW2  16384    // 128*128

// Scratch (no allocation allowed)
__device__ float g_dec[2*100*HW];     // 2 channel-split partials of conv1x1(de,W_cd)
__device__ float g_gatep[2*4*HW];     // 2 partials of gate pre-activation (lowres)
__device__ float g_enc[100*HW2];      // conv1x1(en, W_ce)+b_ce   [b*25+k][i][j]
__device__ float g_raw[100*HW2];      // pre-softmax kernel logits
__device__ float g_det[4*HW*256];     // de transposed: [b][pix][c] (channel-interleaved)

typedef unsigned long long u64;

__device__ __forceinline__ u64 pack2(float x, float y){
    u64 r; asm("mov.b64 %0, {%1, %2};" : "=l"(r) : "f"(x), "f"(y)); return r;
}
__device__ __forceinline__ void unpack2(u64 v, float &x, float &y){
    asm("mov.b64 {%0, %1}, %2;" : "=f"(x), "=f"(y) : "l"(v));
}
__device__ __forceinline__ void ffma2(u64 &d, u64 a, u64 b){
    asm("fma.rn.f32x2 %0, %1, %2, %0;" : "+l"(d) : "l"(a), "l"(b));
}

// ---------------------------------------------------------------------------
// K1: 2-way channel-split conv1x1 of de -> 25 dec partials + gate partial.
// Also emits de_t[b][pix][c] (channel-interleaved transpose) via smem.
// 32768 threads: split s = bx>>6, 256 pixels per block.
// ---------------------------------------------------------------------------
__global__ __launch_bounds__(256) void k1_dec_gate(
        const float* __restrict__ de, const float* __restrict__ W_cd,
        const float* __restrict__ W_gate)
{
    __shared__ __align__(16) float swf[128*28];   // [c_local][28] outputs 0..24=Wcd,25=Wgate
    __shared__ __align__(16) float sT[256*17];    // transpose buffer, 16 c per chunk, pad 17

    int tid = threadIdx.x;
    int s = blockIdx.x >> 6;            // channel split 0/1
    int c0 = s << 7;                    // 0 or 128
    int tbase = (blockIdx.x & 63) << 8; // pixel base (0..16383)
    int b = tbase >> 12;
    int px0 = tbase & 4095;
    int pix = px0 + tid;

    for (int idx = tid; idx < 128*28; idx += 256){
        int c = idx / 28, r = idx - c*28;
        float w = 0.f;
        if (r < 25)       w = W_cd[r*256 + c0 + c];
        else if (r == 25) w = W_gate[c0 + c];
        swf[idx] = w;
    }
    __syncthreads();

    const float* dp = de + ((b<<8) + c0)*HW + pix;
    const ulonglong2* pw2 = (const ulonglong2*)swf;

    u64 acc[13];
    #pragma unroll
    for (int p=0;p<13;p++) acc[p] = 0ULL;

    int tid17 = tid*17;
    for (int chunk = 0; chunk < 8; chunk++){
        #pragma unroll
        for (int cc = 0; cc < 16; cc++){
            int c = (chunk<<4) + cc;
            float v = dp[c*HW];
            sT[tid17 + cc] = v;
            u64 vd = pack2(v, v);
            const ulonglong2* wc = pw2 + c*7;
            #pragma unroll
            for (int p=0;p<6;p++){
                ulonglong2 w = wc[p];
                ffma2(acc[2*p],   vd, w.x);
                ffma2(acc[2*p+1], vd, w.y);
            }
            ffma2(acc[12], vd, wc[6].x);
        }
        __syncthreads();
        // flush 256px x 16c to de_t
        #pragma unroll
        for (int it=0; it<4; it++){
            int v = tid + (it<<8);           // 0..1023
            int pxl = v >> 2, q = v & 3;
            int sb = pxl*17 + (q<<2);
            float4 o4 = make_float4(sT[sb], sT[sb+1], sT[sb+2], sT[sb+3]);
            *(float4*)&g_det[(((b<<12) + px0 + pxl)<<8) + c0 + (chunk<<4) + (q<<2)] = o4;
        }
        __syncthreads();
    }

    float o[26];
    #pragma unroll
    for (int p=0;p<13;p++) unpack2(acc[p], o[2*p], o[2*p+1]);
    #pragma unroll
    for (int k=0;k<25;k++) g_dec[((s*100) + b*25 + k)*HW + pix] = o[k];
    g_gatep[((s<<2) + b)*HW + pix] = o[25];
}

// ---------------------------------------------------------------------------
// K2: enc[b,k,i,j] = sum_c en[b,c,i,j]*W_ce[k,c] + b_ce[k]
// 65536 threads, 1 hires pixel each; weights broadcast from smem via LDS.128.
// ---------------------------------------------------------------------------
__global__ __launch_bounds__(256) void k2_enc(
        const float* __restrict__ en, const float* __restrict__ W_ce,
        const float* __restrict__ b_ce)
{
    __shared__ __align__(16) float swf[256*28];
    int tid = threadIdx.x;
    for (int idx = tid; idx < 256*28; idx += 256){
        int c = idx / 28, r = idx - c*28;
        swf[idx] = (r < 25) ? W_ce[r*256 + c] : 0.f;
    }
    __syncthreads();

    int t = blockIdx.x*256 + tid;        // 65536
    int b = t >> 14, px = t & 16383;
    const float* ep = en + (b<<8)*HW2 + px;
    const ulonglong2* pw2 = (const ulonglong2*)swf;

    u64 acc[13];
    #pragma unroll
    for (int p=0;p<13;p++) acc[p] = 0ULL;

    #pragma unroll 8
    for (int c=0;c<256;c++){
        float v = ep[c*HW2];
        u64 vd = pack2(v, v);
        const ulonglong2* wc = pw2 + c*7;
        #pragma unroll
        for (int p=0;p<6;p++){
            ulonglong2 w = wc[p];
            ffma2(acc[2*p],   vd, w.x);
            ffma2(acc[2*p+1], vd, w.y);
        }
        ffma2(acc[12], vd, wc[6].x);
    }

    float o[26];
    #pragma unroll
    for (int p=0;p<13;p++) unpack2(acc[p], o[2*p], o[2*p+1]);
    #pragma unroll
    for (int k=0;k<25;k++) g_enc[(b*25+k)*HW2 + px] = o[k] + b_ce[k];
}

// ---------------------------------------------------------------------------
// K3: raw = dw3x3(enc) + up2(dw3x3(dec0+dec1)) + 2*b_dw  (bias appears twice)
// ---------------------------------------------------------------------------
__global__ __launch_bounds__(256) void k3_raw(
        const float* __restrict__ W_dw, const float* __restrict__ b_dw)
{
    int bk = blockIdx.y;                 // b*25 + k
    int k = bk % 25;
    __shared__ float sw[9];
    __shared__ float sbias;
    if (threadIdx.x < 9)  sw[threadIdx.x] = W_dw[k*9 + threadIdx.x];
    if (threadIdx.x == 9) sbias = b_dw[k];
    __syncthreads();

    int p = blockIdx.x*256 + threadIdx.x;
    int i = p >> 7, j = p & 127;
    const float* e  = g_enc + bk*HW2;
    const float* d0 = g_dec + bk*HW;
    const float* d1 = g_dec + (100 + bk)*HW;

    float acc = 2.f * sbias;
    #pragma unroll
    for (int u=0;u<3;u++){
        int ii = i + u - 1;
        if ((unsigned)ii < 128u){
            #pragma unroll
            for (int v=0;v<3;v++){
                int jj = j + v - 1;
                if ((unsigned)jj < 128u) acc += e[ii*128 + jj] * sw[u*3+v];
            }
        }
    }
    int h = i >> 1, w = j >> 1;
    #pragma unroll
    for (int u=0;u<3;u++){
        int hh = h + u - 1;
        if ((unsigned)hh < 64u){
            #pragma unroll
            for (int v=0;v<3;v++){
                int ww = w + v - 1;
                if ((unsigned)ww < 64u)
                    acc += (d0[hh*64 + ww] + d1[hh*64 + ww]) * sw[u*3+v];
            }
        }
    }
    g_raw[bk*HW2 + p] = acc;
}

// ---------------------------------------------------------------------------
// K4: softmax -> 25 weights (packed (w,w)); carafe over de_t staged in smem as
// channel-packed float4 (1 LDS.128 feeds 4 channels = 2 FFMA2); fused gate
// blend. Block: 8x4 lowres tile, 128 threads (32 px x 4 subpixels).
// Grid: (8, 16, 4) = 512 blocks.
// ---------------------------------------------------------------------------
__global__ __launch_bounds__(128) void k4_out(
        const float* __restrict__ en, const float* __restrict__ b_gate,
        float* __restrict__ out)
{
    __shared__ __align__(16) float4 sde[96*17];   // [px<96][16 groups + pad]

    int tid = threadIdx.x;
    int sub = tid & 3, lp = tid >> 2;      // lp: 0..31
    int lw = lp & 7,  lh = lp >> 3;        // 8 x 4 lowres tile
    int b  = blockIdx.z;
    int w0 = blockIdx.x * 8, h0 = blockIdx.y * 4;
    int hcur = h0 + lh, wcur = w0 + lw;
    int i = 2*hcur + (sub >> 1), j = 2*wcur + (sub & 1);

    // softmax weights
    float r[25];
    const float* rp = g_raw + (b*25)*HW2 + (i<<7) + j;
    #pragma unroll
    for (int k=0;k<25;k++) r[k] = rp[k*HW2];
    float m = r[0];
    #pragma unroll
    for (int k=1;k<25;k++) m = fmaxf(m, r[k]);
    float ssum = 0.f;
    #pragma unroll
    for (int k=0;k<25;k++){ r[k] = __expf(r[k]-m); ssum += r[k]; }
    float inv = 1.f / ssum;
    u64 wp[25];
    #pragma unroll
    for (int k=0;k<25;k++){ float wv = r[k]*inv; wp[k] = pack2(wv, wv); }

    // gate (sum of 2 partials + bias)
    int lpix = hcur*64 + wcur;
    float gpre = g_gatep[b*HW + lpix] + g_gatep[(4+b)*HW + lpix] + b_gate[0];
    float gt = 1.f / (1.f + __expf(-gpre));
    float ga = 1.f - gt;

    int outbase = (b<<22) + (i<<7) + j;
    int tapbase = (lh*12 + lw)*17;

    for (int chunk = 0; chunk < 4; chunk++){
        int c0 = chunk << 6;
        // stage 96 px x 64 ch from de_t (zero-padded halo)
        #pragma unroll
        for (int it = 0; it < 12; it++){
            int idx = tid + (it << 7);       // 0..1535
            int px = idx >> 4, g = idx & 15;
            int py = px / 12, pxx = px - py*12;
            int hh = h0 - 2 + py, ww = w0 - 2 + pxx;
            float4 v = make_float4(0.f,0.f,0.f,0.f);
            if ((unsigned)hh < 64u && (unsigned)ww < 64u)
                v = *(const float4*)&g_det[(((b<<12) + (hh<<6) + ww)<<8) + c0 + (g<<2)];
            sde[px*17 + g] = v;
        }
        __syncthreads();

        const ulonglong2* spb = (const ulonglong2*)sde;
        #pragma unroll
        for (int g = 0; g < 16; g++){
            u64 accA = 0ULL, accB = 0ULL;
            const ulonglong2* sp = spb + tapbase + g;
            #pragma unroll
            for (int dy=0; dy<5; dy++){
                #pragma unroll
                for (int dx=0; dx<5; dx++){
                    ulonglong2 tv = sp[(dy*12 + dx)*17];
                    ffma2(accA, tv.x, wp[dy*5 + dx]);
                    ffma2(accB, tv.y, wp[dy*5 + dx]);
                }
            }
            float a0,a1,a2,a3;
            unpack2(accA, a0, a1); unpack2(accB, a2, a3);
            int ob = outbase + ((c0 + (g<<2)) << 14);
            out[ob]             = fmaf(gt, en[ob],             ga*a0);
            out[ob + (1<<14)]   = fmaf(gt, en[ob + (1<<14)],   ga*a1);
            out[ob + (2<<14)]   = fmaf(gt, en[ob + (2<<14)],   ga*a2);
            out[ob + (3<<14)]   = fmaf(gt, en[ob + (3<<14)],   ga*a3);
        }
        __syncthreads();
    }
}

// ---------------------------------------------------------------------------
extern "C" void kernel_launch(void* const* d_in, const int* in_sizes, int n_in,
                              void* d_out, int out_size)
{
    const float* en     = (const float*)d_in[0];
    const float* de     = (const float*)d_in[1];
    const float* W_gate = (const float*)d_in[2];
    const float* b_gate = (const float*)d_in[3];
    const float* W_ce   = (const float*)d_in[4];
    const float* b_ce   = (const float*)d_in[5];
    const float* W_cd   = (const float*)d_in[6];
    const float* W_dw   = (const float*)d_in[7];
    const float* b_dw   = (const float*)d_in[8];
    float* out = (float*)d_out;

    k1_dec_gate<<<128, 256>>>(de, W_cd, W_gate);
    k2_enc<<<256, 256>>>(en, W_ce, b_ce);
    k3_raw<<<dim3(64, 100), 256>>>(W_dw, b_dw);
    k4_out<<<dim3(8, 16, 4), 128>>>(en, b_gate, out);
}

// round 3
// speedup vs baseline: 1.7892x; 1.2538x over previous
#include <cuda_runtime.h>

#define HW   4096     // 64*64
#define HW2  16384    // 128*128

// Scratch (no allocation allowed)
__device__ float g_decp[4*100*HW];    // 4 channel-split partials of conv1x1(de,W_cd)
__device__ float g_gatep[4*4*HW];     // 4 partials of gate pre-activation (lowres)
__device__ float g_encp[2*100*HW2];   // 2 partials of conv1x1(en,W_ce) (+b_ce in s=0)
__device__ float g_dwd[100*HW];       // dw3x3(dec)+b_dw on lowres
__device__ float g_raw[100*HW2];      // pre-softmax kernel logits
__device__ float g_det[4*HW*256];     // de transposed: [b][pix][c]

typedef unsigned long long u64;

__device__ __forceinline__ u64 pack2(float x, float y){
    u64 r; asm("mov.b64 %0, {%1, %2};" : "=l"(r) : "f"(x), "f"(y)); return r;
}
__device__ __forceinline__ void unpack2(u64 v, float &x, float &y){
    asm("mov.b64 {%0, %1}, %2;" : "=f"(x), "=f"(y) : "l"(v));
}
__device__ __forceinline__ void ffma2(u64 &d, u64 a, u64 b){
    asm("fma.rn.f32x2 %0, %1, %2, %0;" : "+l"(d) : "l"(a), "l"(b));
}

// ---------------------------------------------------------------------------
// K1: 4-way channel-split conv1x1 of de -> 25 dec partials + gate partial.
// Also emits this split's 64-channel slice of de_t[b][pix][c].
// grid 256 = 4 splits x 64 pixel-blocks, 256 thr.
// ---------------------------------------------------------------------------
__global__ __launch_bounds__(256) void k1_dec_gate(
        const float* __restrict__ de, const float* __restrict__ W_cd,
        const float* __restrict__ W_gate)
{
    __shared__ __align__(16) float swf[64*28];    // [c_local][28]: 0..24 W_cd, 25 W_gate
    __shared__ __align__(16) float sT[256*17];    // transpose buffer (16 ch chunks)

    int tid = threadIdx.x;
    int s = blockIdx.x >> 6;            // split 0..3
    int c0 = s << 6;                    // 0,64,128,192
    int tbase = (blockIdx.x & 63) << 8;
    int b = tbase >> 12;
    int px0 = tbase & 4095;
    int pix = px0 + tid;

    for (int idx = tid; idx < 64*28; idx += 256){
        int c = idx / 28, r = idx - c*28;
        float w = 0.f;
        if (r < 25)       w = W_cd[r*256 + c0 + c];
        else if (r == 25) w = W_gate[c0 + c];
        swf[idx] = w;
    }
    __syncthreads();

    const float* dp = de + ((b<<8) + c0)*HW + pix;
    const ulonglong2* pw2 = (const ulonglong2*)swf;

    u64 acc[13];
    #pragma unroll
    for (int p=0;p<13;p++) acc[p] = 0ULL;

    int tid17 = tid*17;
    for (int chunk = 0; chunk < 4; chunk++){
        #pragma unroll
        for (int cc = 0; cc < 16; cc++){
            int c = (chunk<<4) + cc;
            float v = dp[c*HW];
            sT[tid17 + cc] = v;
            u64 vd = pack2(v, v);
            const ulonglong2* wc = pw2 + c*7;
            #pragma unroll
            for (int p=0;p<6;p++){
                ulonglong2 w = wc[p];
                ffma2(acc[2*p],   vd, w.x);
                ffma2(acc[2*p+1], vd, w.y);
            }
            ffma2(acc[12], vd, wc[6].x);
        }
        __syncthreads();
        #pragma unroll
        for (int it=0; it<4; it++){
            int v = tid + (it<<8);           // 0..1023
            int pxl = v >> 2, q = v & 3;
            int sb = pxl*17 + (q<<2);
            float4 o4 = make_float4(sT[sb], sT[sb+1], sT[sb+2], sT[sb+3]);
            *(float4*)&g_det[(((b<<12) + px0 + pxl)<<8) + c0 + (chunk<<4) + (q<<2)] = o4;
        }
        __syncthreads();
    }

    float o[26];
    #pragma unroll
    for (int p=0;p<13;p++) unpack2(acc[p], o[2*p], o[2*p+1]);
    #pragma unroll
    for (int k=0;k<25;k++) g_decp[((s*100) + b*25 + k)*HW + pix] = o[k];
    g_gatep[((s<<2) + b)*HW + pix] = o[25];
}

// ---------------------------------------------------------------------------
// K2: 2-way channel-split conv1x1 of en -> 25 enc partials (+b_ce in split 0).
// grid 512 = 2 splits x 256 pixel-blocks, 256 thr.
// ---------------------------------------------------------------------------
__global__ __launch_bounds__(256) void k2_enc(
        const float* __restrict__ en, const float* __restrict__ W_ce,
        const float* __restrict__ b_ce)
{
    __shared__ __align__(16) float swf[128*28];
    int tid = threadIdx.x;
    int s = blockIdx.x >> 8;
    int c0 = s << 7;
    for (int idx = tid; idx < 128*28; idx += 256){
        int c = idx / 28, r = idx - c*28;
        swf[idx] = (r < 25) ? W_ce[r*256 + c0 + c] : 0.f;
    }
    __syncthreads();

    int t = (blockIdx.x & 255)*256 + tid;   // 65536 pixels
    int b = t >> 14, px = t & 16383;
    const float* ep = en + ((b<<8) + c0)*HW2 + px;
    const ulonglong2* pw2 = (const ulonglong2*)swf;

    u64 acc[13];
    #pragma unroll
    for (int p=0;p<13;p++) acc[p] = 0ULL;

    #pragma unroll 8
    for (int c=0;c<128;c++){
        float v = ep[c*HW2];
        u64 vd = pack2(v, v);
        const ulonglong2* wc = pw2 + c*7;
        #pragma unroll
        for (int p=0;p<6;p++){
            ulonglong2 w = wc[p];
            ffma2(acc[2*p],   vd, w.x);
            ffma2(acc[2*p+1], vd, w.y);
        }
        ffma2(acc[12], vd, wc[6].x);
    }

    float o[26];
    #pragma unroll
    for (int p=0;p<13;p++) unpack2(acc[p], o[2*p], o[2*p+1]);
    #pragma unroll
    for (int k=0;k<25;k++){
        float bias = (s == 0) ? b_ce[k] : 0.f;
        g_encp[(s*100 + b*25 + k)*HW2 + px] = o[k] + bias;
    }
}

// ---------------------------------------------------------------------------
// K3a: dwd[bk][h,w] = dw3x3(sum of 4 dec partials)[h,w] + b_dw[k]   (lowres)
// ---------------------------------------------------------------------------
__global__ __launch_bounds__(256) void k3a_dwd(
        const float* __restrict__ W_dw, const float* __restrict__ b_dw)
{
    int bk = blockIdx.y;
    int k = bk % 25;
    __shared__ float sw[9];
    __shared__ float sbias;
    if (threadIdx.x < 9)  sw[threadIdx.x] = W_dw[k*9 + threadIdx.x];
    if (threadIdx.x == 9) sbias = b_dw[k];
    __syncthreads();

    int p = blockIdx.x*256 + threadIdx.x;   // 4096 px
    int h = p >> 6, w = p & 63;
    const float* d0 = g_decp + bk*HW;
    const float* d1 = g_decp + (100 + bk)*HW;
    const float* d2 = g_decp + (200 + bk)*HW;
    const float* d3 = g_decp + (300 + bk)*HW;

    float acc = sbias;
    #pragma unroll
    for (int u=0;u<3;u++){
        int hh = h + u - 1;
        if ((unsigned)hh < 64u){
            #pragma unroll
            for (int v=0;v<3;v++){
                int ww = w + v - 1;
                if ((unsigned)ww < 64u){
                    int o = hh*64 + ww;
                    acc += (d0[o] + d1[o] + d2[o] + d3[o]) * sw[u*3+v];
                }
            }
        }
    }
    g_dwd[bk*HW + p] = acc;
}

// ---------------------------------------------------------------------------
// K3b: raw[bk][i,j] = dw3x3(enc0+enc1)[i,j] + b_dw[k] + dwd[bk][i/2,j/2]
// ---------------------------------------------------------------------------
__global__ __launch_bounds__(256) void k3b_raw(
        const float* __restrict__ W_dw, const float* __restrict__ b_dw)
{
    int bk = blockIdx.y;
    int k = bk % 25;
    __shared__ float sw[9];
    __shared__ float sbias;
    if (threadIdx.x < 9)  sw[threadIdx.x] = W_dw[k*9 + threadIdx.x];
    if (threadIdx.x == 9) sbias = b_dw[k];
    __syncthreads();

    int p = blockIdx.x*256 + threadIdx.x;   // 16384 px
    int i = p >> 7, j = p & 127;
    const float* e0 = g_encp + bk*HW2;
    const float* e1 = g_encp + (100 + bk)*HW2;

    float acc = sbias;
    #pragma unroll
    for (int u=0;u<3;u++){
        int ii = i + u - 1;
        if ((unsigned)ii < 128u){
            #pragma unroll
            for (int v=0;v<3;v++){
                int jj = j + v - 1;
                if ((unsigned)jj < 128u){
                    int o = ii*128 + jj;
                    acc += (e0[o] + e1[o]) * sw[u*3+v];
                }
            }
        }
    }
    acc += g_dwd[bk*HW + (i>>1)*64 + (j>>1)];
    g_raw[bk*HW2 + p] = acc;
}

// ---------------------------------------------------------------------------
// K4: softmax -> 25 (w,w)-packed weights; carafe over de_t staged in smem as
// channel-packed float4; fused gate blend. 2-way channel split.
// Block: 8x4 lowres tile, 128 thr. Grid: (8, 16, 4b*2s) = 1024 blocks.
// ---------------------------------------------------------------------------
__global__ __launch_bounds__(128) void k4_out(
        const float* __restrict__ en, const float* __restrict__ b_gate,
        float* __restrict__ out)
{
    __shared__ __align__(16) float4 sde[96*17];   // [px<96][16 groups + pad]

    int tid = threadIdx.x;
    int sub = tid & 3, lp = tid >> 2;      // lp: 0..31
    int lw = lp & 7,  lh = lp >> 3;        // 8 x 4 lowres tile
    int z  = blockIdx.z;
    int b  = z >> 1, s = z & 1;
    int csplit = s << 7;                   // 0 or 128
    int w0 = blockIdx.x * 8, h0 = blockIdx.y * 4;
    int hcur = h0 + lh, wcur = w0 + lw;
    int i = 2*hcur + (sub >> 1), j = 2*wcur + (sub & 1);

    // softmax weights
    float r[25];
    const float* rp = g_raw + (b*25)*HW2 + (i<<7) + j;
    #pragma unroll
    for (int k=0;k<25;k++) r[k] = rp[k*HW2];
    float m = r[0];
    #pragma unroll
    for (int k=1;k<25;k++) m = fmaxf(m, r[k]);
    float ssum = 0.f;
    #pragma unroll
    for (int k=0;k<25;k++){ r[k] = __expf(r[k]-m); ssum += r[k]; }
    float inv = 1.f / ssum;
    u64 wp[25];
    #pragma unroll
    for (int k=0;k<25;k++){ float wv = r[k]*inv; wp[k] = pack2(wv, wv); }

    // gate (sum of 4 partials + bias)
    int lpix = hcur*64 + wcur;
    float gpre = g_gatep[b*HW + lpix] + g_gatep[(4+b)*HW + lpix]
               + g_gatep[(8+b)*HW + lpix] + g_gatep[(12+b)*HW + lpix] + b_gate[0];
    float gt = 1.f / (1.f + __expf(-gpre));
    float ga = 1.f - gt;

    int outbase = (b<<22) + (i<<7) + j;
    int tapbase = (lh*12 + lw)*17;

    for (int chunk = 0; chunk < 2; chunk++){
        int c0 = csplit + (chunk << 6);
        #pragma unroll
        for (int it = 0; it < 12; it++){
            int idx = tid + (it << 7);       // 0..1535
            int px = idx >> 4, g = idx & 15;
            int py = px / 12, pxx = px - py*12;
            int hh = h0 - 2 + py, ww = w0 - 2 + pxx;
            float4 v = make_float4(0.f,0.f,0.f,0.f);
            if ((unsigned)hh < 64u && (unsigned)ww < 64u)
                v = *(const float4*)&g_det[(((b<<12) + (hh<<6) + ww)<<8) + c0 + (g<<2)];
            sde[px*17 + g] = v;
        }
        __syncthreads();

        const ulonglong2* spb = (const ulonglong2*)sde;
        #pragma unroll
        for (int g = 0; g < 16; g++){
            u64 accA = 0ULL, accB = 0ULL;
            const ulonglong2* sp = spb + tapbase + g;
            #pragma unroll
            for (int dy=0; dy<5; dy++){
                #pragma unroll
                for (int dx=0; dx<5; dx++){
                    ulonglong2 tv = sp[(dy*12 + dx)*17];
                    ffma2(accA, tv.x, wp[dy*5 + dx]);
                    ffma2(accB, tv.y, wp[dy*5 + dx]);
                }
            }
            float a0,a1,a2,a3;
            unpack2(accA, a0, a1); unpack2(accB, a2, a3);
            int ob = outbase + ((c0 + (g<<2)) << 14);
            out[ob]             = fmaf(gt, en[ob],             ga*a0);
            out[ob + (1<<14)]   = fmaf(gt, en[ob + (1<<14)],   ga*a1);
            out[ob + (2<<14)]   = fmaf(gt, en[ob + (2<<14)],   ga*a2);
            out[ob + (3<<14)]   = fmaf(gt, en[ob + (3<<14)],   ga*a3);
        }
        __syncthreads();
    }
}

// ---------------------------------------------------------------------------
extern "C" void kernel_launch(void* const* d_in, const int* in_sizes, int n_in,
                              void* d_out, int out_size)
{
    const float* en     = (const float*)d_in[0];
    const float* de     = (const float*)d_in[1];
    const float* W_gate = (const float*)d_in[2];
    const float* b_gate = (const float*)d_in[3];
    const float* W_ce   = (const float*)d_in[4];
    const float* b_ce   = (const float*)d_in[5];
    const float* W_cd   = (const float*)d_in[6];
    const float* W_dw   = (const float*)d_in[7];
    const float* b_dw   = (const float*)d_in[8];
    float* out = (float*)d_out;

    k1_dec_gate<<<256, 256>>>(de, W_cd, W_gate);
    k2_enc<<<512, 256>>>(en, W_ce, b_ce);
    k3a_dwd<<<dim3(16, 100), 256>>>(W_dw, b_dw);
    k3b_raw<<<dim3(64, 100), 256>>>(W_dw, b_dw);
    k4_out<<<dim3(8, 16, 8), 128>>>(en, b_gate, out);
}

// round 4
// speedup vs baseline: 1.9265x; 1.0767x over previous
#include <cuda_runtime.h>

#define HW   4096     // 64*64
#define HW2  16384    // 128*128

// Scratch (no allocation allowed)
__device__ float g_decp[8*100*HW];    // 8 channel-split partials of conv1x1(de,W_cd)
__device__ float g_decs[100*HW];      // summed dec
__device__ float g_gatep[8*4*HW];     // 8 partials of gate pre-activation (lowres)
__device__ float g_encp[2*100*HW2];   // 2 partials of conv1x1(en,W_ce) (+b_ce in s=0)
__device__ float g_dwd[100*HW];       // dw3x3(dec)+b_dw on lowres
__device__ float g_wt[100*HW2];       // softmax-normalized carafe weights [b*25+k][pix]
__device__ float g_det[4*HW*256];     // de transposed: [b][pix][c]

typedef unsigned long long u64;

__device__ __forceinline__ u64 pack2(float x, float y){
    u64 r; asm("mov.b64 %0, {%1, %2};" : "=l"(r) : "f"(x), "f"(y)); return r;
}
__device__ __forceinline__ void unpack2(u64 v, float &x, float &y){
    asm("mov.b64 {%0, %1}, %2;" : "=f"(x), "=f"(y) : "l"(v));
}
__device__ __forceinline__ void ffma2(u64 &d, u64 a, u64 b){
    asm("fma.rn.f32x2 %0, %1, %2, %0;" : "+l"(d) : "l"(a), "l"(b));
}

// ---------------------------------------------------------------------------
// K1: 8-way channel-split conv1x1 of de -> 25 dec partials + gate partial.
// Also emits this split's 32-channel slice of de_t[b][pix][c].
// grid 512 = 8 splits x 64 pixel-blocks, 256 thr.
// ---------------------------------------------------------------------------
__global__ __launch_bounds__(256) void k1_dec_gate(
        const float* __restrict__ de, const float* __restrict__ W_cd,
        const float* __restrict__ W_gate)
{
    __shared__ __align__(16) float swf[32*28];
    __shared__ __align__(16) float sT[256*17];

    int tid = threadIdx.x;
    int s = blockIdx.x >> 6;            // split 0..7
    int c0 = s << 5;                    // 32-ch slice base
    int tbase = (blockIdx.x & 63) << 8;
    int b = tbase >> 12;
    int px0 = tbase & 4095;
    int pix = px0 + tid;

    for (int idx = tid; idx < 32*28; idx += 256){
        int c = idx / 28, r = idx - c*28;
        float w = 0.f;
        if (r < 25)       w = W_cd[r*256 + c0 + c];
        else if (r == 25) w = W_gate[c0 + c];
        swf[idx] = w;
    }
    __syncthreads();

    const float* dp = de + ((b<<8) + c0)*HW + pix;
    const ulonglong2* pw2 = (const ulonglong2*)swf;

    u64 acc[13];
    #pragma unroll
    for (int p=0;p<13;p++) acc[p] = 0ULL;

    int tid17 = tid*17;
    for (int chunk = 0; chunk < 2; chunk++){
        #pragma unroll
        for (int cc = 0; cc < 16; cc++){
            int c = (chunk<<4) + cc;
            float v = dp[c*HW];
            sT[tid17 + cc] = v;
            u64 vd = pack2(v, v);
            const ulonglong2* wc = pw2 + c*7;
            #pragma unroll
            for (int p=0;p<6;p++){
                ulonglong2 w = wc[p];
                ffma2(acc[2*p],   vd, w.x);
                ffma2(acc[2*p+1], vd, w.y);
            }
            ffma2(acc[12], vd, wc[6].x);
        }
        __syncthreads();
        #pragma unroll
        for (int it=0; it<4; it++){
            int v = tid + (it<<8);           // 0..1023
            int pxl = v >> 2, q = v & 3;
            int sb = pxl*17 + (q<<2);
            float4 o4 = make_float4(sT[sb], sT[sb+1], sT[sb+2], sT[sb+3]);
            *(float4*)&g_det[(((b<<12) + px0 + pxl)<<8) + c0 + (chunk<<4) + (q<<2)] = o4;
        }
        __syncthreads();
    }

    float o[26];
    #pragma unroll
    for (int p=0;p<13;p++) unpack2(acc[p], o[2*p], o[2*p+1]);
    #pragma unroll
    for (int k=0;k<25;k++) g_decp[((s*100) + b*25 + k)*HW + pix] = o[k];
    g_gatep[((s<<2) + b)*HW + pix] = o[25];
}

// ---------------------------------------------------------------------------
// K2: 2-way channel-split conv1x1 of en -> 25 enc partials (+b_ce in split 0).
// ---------------------------------------------------------------------------
__global__ __launch_bounds__(256) void k2_enc(
        const float* __restrict__ en, const float* __restrict__ W_ce,
        const float* __restrict__ b_ce)
{
    __shared__ __align__(16) float swf[128*28];
    int tid = threadIdx.x;
    int s = blockIdx.x >> 8;
    int c0 = s << 7;
    for (int idx = tid; idx < 128*28; idx += 256){
        int c = idx / 28, r = idx - c*28;
        swf[idx] = (r < 25) ? W_ce[r*256 + c0 + c] : 0.f;
    }
    __syncthreads();

    int t = (blockIdx.x & 255)*256 + tid;   // 65536 pixels
    int b = t >> 14, px = t & 16383;
    const float* ep = en + ((b<<8) + c0)*HW2 + px;
    const ulonglong2* pw2 = (const ulonglong2*)swf;

    u64 acc[13];
    #pragma unroll
    for (int p=0;p<13;p++) acc[p] = 0ULL;

    #pragma unroll 8
    for (int c=0;c<128;c++){
        float v = ep[c*HW2];
        u64 vd = pack2(v, v);
        const ulonglong2* wc = pw2 + c*7;
        #pragma unroll
        for (int p=0;p<6;p++){
            ulonglong2 w = wc[p];
            ffma2(acc[2*p],   vd, w.x);
            ffma2(acc[2*p+1], vd, w.y);
        }
        ffma2(acc[12], vd, wc[6].x);
    }

    float o[26];
    #pragma unroll
    for (int p=0;p<13;p++) unpack2(acc[p], o[2*p], o[2*p+1]);
    #pragma unroll
    for (int k=0;k<25;k++){
        float bias = (s == 0) ? b_ce[k] : 0.f;
        g_encp[(s*100 + b*25 + k)*HW2 + px] = o[k] + bias;
    }
}

// ---------------------------------------------------------------------------
// K3s: sum the 8 dec partials into one plane.
// ---------------------------------------------------------------------------
__global__ __launch_bounds__(256) void k3s_sum()
{
    int t = blockIdx.x*256 + threadIdx.x;     // 409600
    float a = 0.f;
    #pragma unroll
    for (int s=0;s<8;s++) a += g_decp[s*100*HW + t];
    g_decs[t] = a;
}

// ---------------------------------------------------------------------------
// K3a: dwd[bk][h,w] = dw3x3(decs)[h,w] + b_dw[k]   (lowres)
// ---------------------------------------------------------------------------
__global__ __launch_bounds__(256) void k3a_dwd(
        const float* __restrict__ W_dw, const float* __restrict__ b_dw)
{
    int bk = blockIdx.y;
    int k = bk % 25;
    __shared__ float sw[9];
    __shared__ float sbias;
    if (threadIdx.x < 9)  sw[threadIdx.x] = W_dw[k*9 + threadIdx.x];
    if (threadIdx.x == 9) sbias = b_dw[k];
    __syncthreads();

    int p = blockIdx.x*256 + threadIdx.x;   // 4096 px
    int h = p >> 6, w = p & 63;
    const float* d = g_decs + bk*HW;

    float acc = sbias;
    #pragma unroll
    for (int u=0;u<3;u++){
        int hh = h + u - 1;
        if ((unsigned)hh < 64u){
            #pragma unroll
            for (int v=0;v<3;v++){
                int ww = w + v - 1;
                if ((unsigned)ww < 64u) acc += d[hh*64 + ww] * sw[u*3+v];
            }
        }
    }
    g_dwd[bk*HW + p] = acc;
}

// ---------------------------------------------------------------------------
// K3b: fused raw + softmax -> normalized weights g_wt[bk][pix].
// Block = 16x8 hires tile, 128 thr. Stages all 25 enc-sum halo tiles (18x10)
// plus dwd, W_dw, b_dw with one sync; each thread computes 25 raw logits,
// softmaxes in regs, stores 25 coalesced planes.
// Grid (8, 16, 4) = 512 blocks.
// ---------------------------------------------------------------------------
__global__ __launch_bounds__(128) void k3b_softmax(
        const float* __restrict__ W_dw, const float* __restrict__ b_dw)
{
    __shared__ float senc[25*180];   // [k][row 0..9][col 0..17]
    __shared__ float sdwd[25*32];    // [k][lr 0..3][lc 0..7]
    __shared__ float swd[225];
    __shared__ float sbd[25];

    int tid = threadIdx.x;
    int b = blockIdx.z;
    int j0 = blockIdx.x << 4;        // 16-wide
    int i0 = blockIdx.y << 3;        // 8-high
    const float* e0 = g_encp + (b*25)*HW2;
    const float* e1 = g_encp + (100 + b*25)*HW2;

    for (int idx = tid; idx < 4500; idx += 128){
        int k = idx / 180;
        int rem = idx - k*180;
        int r = rem / 18, c = rem - r*18;
        int gi = i0 - 1 + r, gj = j0 - 1 + c;
        float v = 0.f;
        if ((unsigned)gi < 128u && (unsigned)gj < 128u){
            int o = k*HW2 + (gi<<7) + gj;
            v = e0[o] + e1[o];
        }
        senc[idx] = v;
    }
    for (int idx = tid; idx < 800; idx += 128){
        int k = idx >> 5, px = idx & 31;
        int lr = px >> 3, lc = px & 7;
        sdwd[idx] = g_dwd[(b*25+k)*HW + ((i0>>1)+lr)*64 + (j0>>1)+lc];
    }
    if (tid < 25) sbd[tid] = b_dw[tid];
    for (int idx = tid; idx < 225; idx += 128) swd[idx] = W_dw[idx];
    __syncthreads();

    int tx = tid & 15, ty = tid >> 4;
    int dwo = ((ty>>1)<<3) + (tx>>1);

    float r[25];
    #pragma unroll
    for (int k=0;k<25;k++){
        float acc = sbd[k];
        const float* sp = senc + k*180 + ty*18 + tx;
        const float* wk = swd + k*9;
        #pragma unroll
        for (int u=0;u<3;u++){
            #pragma unroll
            for (int v=0;v<3;v++) acc = fmaf(sp[u*18+v], wk[u*3+v], acc);
        }
        r[k] = acc + sdwd[(k<<5) + dwo];
    }

    float m = r[0];
    #pragma unroll
    for (int k=1;k<25;k++) m = fmaxf(m, r[k]);
    float ssum = 0.f;
    #pragma unroll
    for (int k=0;k<25;k++){ r[k] = __expf(r[k]-m); ssum += r[k]; }
    float inv = 1.f / ssum;

    int p = (i0+ty)*128 + j0 + tx;
    #pragma unroll
    for (int k=0;k<25;k++) g_wt[(b*25+k)*HW2 + p] = r[k]*inv;
}

// ---------------------------------------------------------------------------
// K4: carafe + gate blend. 4-way channel split (one 64-ch chunk per block).
// Weights come pre-normalized from g_wt. Block: 8x4 lowres tile, 128 thr.
// Grid: (8, 16, 4b*4s) = 2048 blocks.
// ---------------------------------------------------------------------------
__global__ __launch_bounds__(128) void k4_out(
        const float* __restrict__ en, const float* __restrict__ b_gate,
        float* __restrict__ out)
{
    __shared__ __align__(16) float4 sde[96*17];

    int tid = threadIdx.x;
    int sub = tid & 3, lp = tid >> 2;      // lp: 0..31
    int lw = lp & 7,  lh = lp >> 3;        // 8 x 4 lowres tile
    int z  = blockIdx.z;
    int b  = z >> 2, s = z & 3;
    int c0 = s << 6;
    int w0 = blockIdx.x * 8, h0 = blockIdx.y * 4;
    int hcur = h0 + lh, wcur = w0 + lw;
    int i = 2*hcur + (sub >> 1), j = 2*wcur + (sub & 1);

    // stage 96 px x 64 ch from de_t (zero-padded halo)
    #pragma unroll
    for (int it = 0; it < 12; it++){
        int idx = tid + (it << 7);       // 0..1535
        int px = idx >> 4, g = idx & 15;
        int py = px / 12, pxx = px - py*12;
        int hh = h0 - 2 + py, ww = w0 - 2 + pxx;
        float4 v = make_float4(0.f,0.f,0.f,0.f);
        if ((unsigned)hh < 64u && (unsigned)ww < 64u)
            v = *(const float4*)&g_det[(((b<<12) + (hh<<6) + ww)<<8) + c0 + (g<<2)];
        sde[px*17 + g] = v;
    }

    // normalized weights
    u64 wp[25];
    const float* wtp = g_wt + (b*25)*HW2 + (i<<7) + j;
    #pragma unroll
    for (int k=0;k<25;k++){ float wv = wtp[k*HW2]; wp[k] = pack2(wv, wv); }

    // gate (sum of 8 partials + bias)
    int lpix = hcur*64 + wcur;
    float gpre = b_gate[0];
    #pragma unroll
    for (int ss=0;ss<8;ss++) gpre += g_gatep[((ss<<2)+b)*HW + lpix];
    float gt = 1.f / (1.f + __expf(-gpre));
    float ga = 1.f - gt;

    int outbase = (b<<22) + (i<<7) + j;
    int tapbase = (lh*12 + lw)*17;

    __syncthreads();

    const ulonglong2* spb = (const ulonglong2*)sde;
    #pragma unroll
    for (int g = 0; g < 16; g++){
        u64 accA = 0ULL, accB = 0ULL;
        const ulonglong2* sp = spb + tapbase + g;
        #pragma unroll
        for (int dy=0; dy<5; dy++){
            #pragma unroll
            for (int dx=0; dx<5; dx++){
                ulonglong2 tv = sp[(dy*12 + dx)*17];
                ffma2(accA, tv.x, wp[dy*5 + dx]);
                ffma2(accB, tv.y, wp[dy*5 + dx]);
            }
        }
        float a0,a1,a2,a3;
        unpack2(accA, a0, a1); unpack2(accB, a2, a3);
        int ob = outbase + ((c0 + (g<<2)) << 14);
        out[ob]             = fmaf(gt, en[ob],             ga*a0);
        out[ob + (1<<14)]   = fmaf(gt, en[ob + (1<<14)],   ga*a1);
        out[ob + (2<<14)]   = fmaf(gt, en[ob + (2<<14)],   ga*a2);
        out[ob + (3<<14)]   = fmaf(gt, en[ob + (3<<14)],   ga*a3);
    }
}

// ---------------------------------------------------------------------------
extern "C" void kernel_launch(void* const* d_in, const int* in_sizes, int n_in,
                              void* d_out, int out_size)
{
    const float* en     = (const float*)d_in[0];
    const float* de     = (const float*)d_in[1];
    const float* W_gate = (const float*)d_in[2];
    const float* b_gate = (const float*)d_in[3];
    const float* W_ce   = (const float*)d_in[4];
    const float* b_ce   = (const float*)d_in[5];
    const float* W_cd   = (const float*)d_in[6];
    const float* W_dw   = (const float*)d_in[7];
    const float* b_dw   = (const float*)d_in[8];
    float* out = (float*)d_out;

    k1_dec_gate<<<512, 256>>>(de, W_cd, W_gate);
    k2_enc<<<512, 256>>>(en, W_ce, b_ce);
    k3s_sum<<<1600, 256>>>();
    k3a_dwd<<<dim3(16, 100), 256>>>(W_dw, b_dw);
    k3b_softmax<<<dim3(8, 16, 4), 128>>>(W_dw, b_dw);
    k4_out<<<dim3(8, 16, 16), 128>>>(en, b_gate, out);
}